// round 1
// baseline (speedup 1.0000x reference)
#include <cuda_runtime.h>
#include <cuda_bf16.h>
#include <cstdint>

// Chamfer loss, B=8, N=M=4096, D=3.
// Direction-fused kernel: blockIdx.z = 0 -> min over targets for each input
// point; blockIdx.z = 1 -> roles swapped. Each thread owns one query point,
// scans all 4096 targets held in SMEM tiles of 2048 float4 (y0,y1,y2,|y|^2).
// Inner loop per pair: 3 FFMA + 1 FMNMX (norm trick, y^2 folded into smem,
// x^2 added once at the end). Broadcast LDS.128 (whole block reads same
// target index) keeps SMEM off the critical path -> fma-pipe bound.

#define B_DIM 8
#define NPTS 4096
#define TPB 256
#define TILE 2048
#define QBLOCKS (NPTS / TPB)          // 16
#define NBLOCKS (QBLOCKS * B_DIM * 2) // 256

__device__ float g_partials[NBLOCKS];

__global__ __launch_bounds__(TPB) void chamfer_main_kernel(
    const float* __restrict__ in_pts,
    const float* __restrict__ tg_pts)
{
    const int dir = blockIdx.z;
    const float* __restrict__ qset = dir ? tg_pts : in_pts;
    const float* __restrict__ tset = dir ? in_pts : tg_pts;
    const int b = blockIdx.y;
    const int qi = blockIdx.x * TPB + threadIdx.x;   // 0..4095

    // Load this thread's query point, precompute -2*x and |x|^2.
    const float* qp = qset + ((size_t)b * NPTS + qi) * 3;
    const float x0 = qp[0], x1 = qp[1], x2 = qp[2];
    const float nx0 = -2.0f * x0, nx1 = -2.0f * x1, nx2 = -2.0f * x2;
    const float xnorm = fmaf(x0, x0, fmaf(x1, x1, x2 * x2));

    __shared__ float4 s_t[TILE];   // 32 KB

    float mn = 3.402823466e38f;

    #pragma unroll
    for (int tile = 0; tile < NPTS / TILE; ++tile) {
        const float* tb = tset + ((size_t)b * NPTS + tile * TILE) * 3;
        __syncthreads();           // protect previous tile's readers
        // Cooperative load + |y|^2 precompute.
        for (int i = threadIdx.x; i < TILE; i += TPB) {
            float y0 = tb[3 * i + 0];
            float y1 = tb[3 * i + 1];
            float y2 = tb[3 * i + 2];
            float yn = fmaf(y0, y0, fmaf(y1, y1, y2 * y2));
            s_t[i] = make_float4(y0, y1, y2, yn);
        }
        __syncthreads();

        // Scan tile: all threads read the same index -> broadcast LDS.128.
        #pragma unroll 8
        for (int j = 0; j < TILE; ++j) {
            float4 y = s_t[j];
            // d = |y|^2 - 2*x.y   (add |x|^2 after the min)
            float d = fmaf(nx0, y.x, fmaf(nx1, y.y, fmaf(nx2, y.z, y.w)));
            mn = fminf(mn, d);
        }
    }

    // sqdist = max(min_m(|y|^2 - 2xy) + |x|^2, 0); weight by 1/(B*N).
    float sq = fmaxf(mn + xnorm, 0.0f) * (1.0f / (float)(B_DIM * NPTS));

    // Deterministic block reduction.
    __shared__ float red[TPB];
    red[threadIdx.x] = sq;
    __syncthreads();
    #pragma unroll
    for (int s = TPB / 2; s > 0; s >>= 1) {
        if (threadIdx.x < s) red[threadIdx.x] += red[threadIdx.x + s];
        __syncthreads();
    }
    if (threadIdx.x == 0) {
        g_partials[(blockIdx.z * B_DIM + blockIdx.y) * QBLOCKS + blockIdx.x] = red[0];
    }
}

__global__ __launch_bounds__(NBLOCKS) void chamfer_reduce_kernel(float* __restrict__ out)
{
    __shared__ float red[NBLOCKS];
    red[threadIdx.x] = g_partials[threadIdx.x];
    __syncthreads();
    #pragma unroll
    for (int s = NBLOCKS / 2; s > 0; s >>= 1) {
        if (threadIdx.x < s) red[threadIdx.x] += red[threadIdx.x + s];
        __syncthreads();
    }
    if (threadIdx.x == 0) out[0] = red[0];
}

extern "C" void kernel_launch(void* const* d_in, const int* in_sizes, int n_in,
                              void* d_out, int out_size)
{
    const float* in_pts = (const float*)d_in[0];   // [8, 4096, 3]
    const float* tg_pts = (const float*)d_in[1];   // [8, 4096, 3]
    float* out = (float*)d_out;

    dim3 grid(QBLOCKS, B_DIM, 2);
    chamfer_main_kernel<<<grid, TPB>>>(in_pts, tg_pts);
    chamfer_reduce_kernel<<<1, NBLOCKS>>>(out);
}